// round 15
// baseline (speedup 1.0000x reference)
#include <cuda_runtime.h>
#include <cstdint>
#include <cstddef>

// ---------------- problem constants ----------------
#define B_WIN   4096
#define N_TOK   49
#define C_DIM   128
#define NH      4
#define HD      32
#define NWIN    64
#define M_ROWS  (B_WIN * N_TOK)        // 200704
#define SCALE   0.17677669529663687f   // 32^-0.5

// chunking for pipeline overlap (+L2 residency of intermediates)
#define CHUNK_W   1024                  // windows per chunk
#define N_CHUNKS  (B_WIN / CHUNK_W)     // 4
#define CHUNK_M   (CHUNK_W * N_TOK)     // 50176 rows (392 m-blocks)

// ---------------- scratch (no cudaMalloc allowed) ----------------
__device__ __align__(16) float g_qkv[(size_t)M_ROWS * 384];  // tf32 BITS, q pre-scaled
__device__ __align__(16) float g_att[(size_t)M_ROWS * 128];  // tf32 BITS
__device__ __align__(16) float g_bm[NWIN * N_TOK * N_TOK];   // bias[rel] + mask

// ---------------- helpers ----------------
__device__ __forceinline__ uint32_t f2tf32(float f) {
    uint32_t r;
    asm("cvt.rna.tf32.f32 %0, %1;" : "=r"(r) : "f"(f));
    return r;
}
__device__ __forceinline__ void mma_tf32(float c[4], const uint32_t a[4], const uint32_t b[2]) {
    asm volatile(
        "mma.sync.aligned.m16n8k8.row.col.f32.tf32.tf32.f32 "
        "{%0,%1,%2,%3}, {%4,%5,%6,%7}, {%8,%9}, {%0,%1,%2,%3};"
        : "+f"(c[0]), "+f"(c[1]), "+f"(c[2]), "+f"(c[3])
        : "r"(a[0]), "r"(a[1]), "r"(a[2]), "r"(a[3]), "r"(b[0]), "r"(b[1]));
}
__device__ __forceinline__ void cp_async16(uint32_t smem_dst, const void* gsrc) {
    asm volatile("cp.async.ca.shared.global [%0], [%1], 16;\n" :: "r"(smem_dst), "l"(gsrc));
}
__device__ __forceinline__ void cp_commit() { asm volatile("cp.async.commit_group;\n"); }
template <int N>
__device__ __forceinline__ void cp_wait() { asm volatile("cp.async.wait_group %0;\n" :: "n"(N)); }

// ---------------- pre-kernel: g_bm = bias_table[rel_index] + mask ----------------
__global__ void bm_kernel(const float* __restrict__ mask,
                          const float* __restrict__ bias_table,
                          const int*   __restrict__ rel_index)
{
    int idx = blockIdx.x * 256 + threadIdx.x;
    if (idx >= NWIN * N_TOK * N_TOK) return;
    int r = idx % (N_TOK * N_TOK);
    g_bm[idx] = mask[idx] + bias_table[rel_index[r]];
}

// ---------------- tf32 GEMM, cp.async double-buffered (r13-proven, verbatim) --------
#define AS_STRIDE 36
#define BS_STRIDE 136
#define AS_WORDS (128 * AS_STRIDE)
#define BS_WORDS (32 * BS_STRIDE)
#define GEMM_SMEM ((2 * AS_WORDS + 2 * BS_WORDS) * 4)   // 71680 B

template <int NCOLS, bool QKV_OUT, bool A_TF32>
__global__ __launch_bounds__(256, 2)
void gemm_tc_kernel(const float* __restrict__ A,
                    const float* __restrict__ W,
                    const float* __restrict__ bias,
                    float* __restrict__ out)
{
    extern __shared__ float smem[];
    float* As = smem;                 // [2][AS_WORDS]
    float* Bs = smem + 2 * AS_WORDS;  // [2][BS_WORDS]

    const int tid  = threadIdx.x;
    const int lane = tid & 31;
    const int warp = tid >> 5;
    const int wm   = warp >> 2;
    const int wn   = warp & 3;
    const int m0   = blockIdx.y * 128;
    const int n0   = blockIdx.x * 128;

    float acc[4][4][4];
    #pragma unroll
    for (int i = 0; i < 4; i++)
        #pragma unroll
        for (int j = 0; j < 4; j++)
            #pragma unroll
            for (int r = 0; r < 4; r++) acc[i][j][r] = 0.f;

    auto stage_load = [&](int st, int k0) {
        #pragma unroll
        for (int p = 0; p < 4; p++) {
            int idx = tid + p * 256;
            int row = idx >> 3, seg = idx & 7;
            uint32_t dst = (uint32_t)__cvta_generic_to_shared(
                &As[st * AS_WORDS + row * AS_STRIDE + seg * 4]);
            cp_async16(dst, &A[(size_t)(m0 + row) * 128 + k0 + seg * 4]);
        }
        #pragma unroll
        for (int p = 0; p < 4; p++) {
            int idx = tid + p * 256;
            int row = idx >> 5, seg = idx & 31;
            uint32_t dst = (uint32_t)__cvta_generic_to_shared(
                &Bs[st * BS_WORDS + row * BS_STRIDE + seg * 4]);
            cp_async16(dst, &W[(size_t)(k0 + row) * NCOLS + n0 + seg * 4]);
        }
        cp_commit();
    };

    stage_load(0, 0);

    #pragma unroll
    for (int ch = 0; ch < 4; ch++) {
        if (ch < 3) stage_load((ch + 1) & 1, (ch + 1) * 32);
        if (ch < 3) cp_wait<1>(); else cp_wait<0>();
        __syncthreads();

        const float* as = &As[(ch & 1) * AS_WORDS];
        const float* bs = &Bs[(ch & 1) * BS_WORDS];

        #pragma unroll
        for (int kk = 0; kk < 4; kk++) {
            const int k = kk * 8;
            uint32_t af[4][4];
            #pragma unroll
            for (int mt = 0; mt < 4; mt++) {
                int row = wm * 64 + mt * 16 + (lane >> 2);
                int col = k + (lane & 3);
                if (A_TF32) {
                    af[mt][0] = __float_as_uint(as[row * AS_STRIDE + col]);
                    af[mt][1] = __float_as_uint(as[(row + 8) * AS_STRIDE + col]);
                    af[mt][2] = __float_as_uint(as[row * AS_STRIDE + col + 4]);
                    af[mt][3] = __float_as_uint(as[(row + 8) * AS_STRIDE + col + 4]);
                } else {
                    af[mt][0] = f2tf32(as[row * AS_STRIDE + col]);
                    af[mt][1] = f2tf32(as[(row + 8) * AS_STRIDE + col]);
                    af[mt][2] = f2tf32(as[row * AS_STRIDE + col + 4]);
                    af[mt][3] = f2tf32(as[(row + 8) * AS_STRIDE + col + 4]);
                }
            }
            uint32_t bf[4][2];
            #pragma unroll
            for (int nt = 0; nt < 4; nt++) {
                int col = wn * 32 + nt * 8 + (lane >> 2);
                int row = k + (lane & 3);
                bf[nt][0] = f2tf32(bs[row * BS_STRIDE + col]);
                bf[nt][1] = f2tf32(bs[(row + 4) * BS_STRIDE + col]);
            }
            #pragma unroll
            for (int mt = 0; mt < 4; mt++)
                #pragma unroll
                for (int nt = 0; nt < 4; nt++)
                    mma_tf32(acc[mt][nt], af[mt], bf[nt]);
        }
        __syncthreads();
    }

    #pragma unroll
    for (int mt = 0; mt < 4; mt++) {
        #pragma unroll
        for (int nt = 0; nt < 4; nt++) {
            int m = m0 + wm * 64 + mt * 16 + (lane >> 2);
            int n = n0 + wn * 32 + nt * 8 + (lane & 3) * 2;
            float b0 = bias[n], b1 = bias[n + 1];
            float v00 = acc[mt][nt][0] + b0, v01 = acc[mt][nt][1] + b1;
            float v10 = acc[mt][nt][2] + b0, v11 = acc[mt][nt][3] + b1;
            if (QKV_OUT) {
                float s0 = (n     < 128) ? SCALE : 1.f;
                float s1 = (n + 1 < 128) ? SCALE : 1.f;
                *(float2*)&out[(size_t)m * NCOLS + n] = make_float2(
                    __uint_as_float(f2tf32(v00 * s0)), __uint_as_float(f2tf32(v01 * s1)));
                *(float2*)&out[(size_t)(m + 8) * NCOLS + n] = make_float2(
                    __uint_as_float(f2tf32(v10 * s0)), __uint_as_float(f2tf32(v11 * s1)));
            } else {
                *(float2*)&out[(size_t)m * NCOLS + n] = make_float2(v00, v01);
                *(float2*)&out[(size_t)(m + 8) * NCOLS + n] = make_float2(v10, v11);
            }
        }
    }
}

// ---------------- tensor-core window attention (r13-proven, + window base) ----------
#define KS 36
#define VS 40
#define SS 60

__global__ __launch_bounds__(128)
void attn_tc_kernel(int wbase)
{
    const int w = wbase + blockIdx.x;
    const int h = blockIdx.y;

    __shared__ __align__(16) uint32_t Ks[64 * KS];
    __shared__ __align__(16) uint32_t Vs[64 * VS];
    __shared__ __align__(16) uint32_t S [64 * SS];

    const int tid  = threadIdx.x;
    const int lane = tid & 31;
    const int warp = tid >> 5;

    const float* bq = g_qkv + (size_t)w * N_TOK * 384 + h * HD;
    for (int t = tid; t < N_TOK * 8 * 2; t += 128) {
        int tt = t / (N_TOK * 8);                  // 0 = K, 1 = V
        int rem = t - tt * (N_TOK * 8);
        int n = rem >> 3, seg = rem & 7;
        const float* src = bq + n * 384 + (tt + 1) * 128 + seg * 4;
        uint32_t dst = tt == 0
            ? (uint32_t)__cvta_generic_to_shared(&Ks[n * KS + seg * 4])
            : (uint32_t)__cvta_generic_to_shared(&Vs[n * VS + seg * 4]);
        cp_async16(dst, src);
    }
    cp_commit();

    const int rA = warp * 16 + (lane >> 2);
    uint32_t af[4][4];
    {
        const uint32_t* qb = (const uint32_t*)bq;
        int r0 = min(rA,     N_TOK - 1);
        int r1 = min(rA + 8, N_TOK - 1);
        #pragma unroll
        for (int ks = 0; ks < 4; ks++) {
            int col = ks * 8 + (lane & 3);
            af[ks][0] = qb[r0 * 384 + col];
            af[ks][1] = qb[r1 * 384 + col];
            af[ks][2] = qb[r0 * 384 + col + 4];
            af[ks][3] = qb[r1 * 384 + col + 4];
        }
    }

    for (int t = tid; t < 15 * HD; t += 128) {
        int n = N_TOK + (t >> 5), d = t & 31;
        Ks[n * KS + d] = 0u;
        Vs[n * VS + d] = 0u;
    }
    cp_wait<0>();
    __syncthreads();   // only block barrier

    const float* bm = g_bm + (size_t)(w & (NWIN - 1)) * N_TOK * N_TOK;
    {
        #pragma unroll
        for (int nt = 0; nt < 7; nt++) {
            float c[4] = {0.f, 0.f, 0.f, 0.f};
            #pragma unroll
            for (int ks = 0; ks < 4; ks++) {
                int nc = nt * 8 + (lane >> 2);
                int kr = ks * 8 + (lane & 3);
                uint32_t bf[2] = { Ks[nc * KS + kr], Ks[nc * KS + kr + 4] };
                mma_tf32(c, af[ks], bf);
            }
            const int j = nt * 8 + 2 * (lane & 3);
            #pragma unroll
            for (int half = 0; half < 2; half++) {
                int ii = rA + half * 8;
                float o0, o1;
                if (ii < N_TOK) {
                    o0 = (j     < N_TOK) ? c[half * 2]     + __ldg(&bm[ii * N_TOK + j])     : -1e30f;
                    o1 = (j + 1 < N_TOK) ? c[half * 2 + 1] + __ldg(&bm[ii * N_TOK + j + 1]) : -1e30f;
                } else { o0 = 0.f; o1 = 0.f; }
                S[ii * SS + j]     = __float_as_uint(o0);
                S[ii * SS + j + 1] = __float_as_uint(o1);
            }
        }
    }
    __syncwarp();

    {
        const int rend = min(warp * 16 + 16, N_TOK);
        for (int i = warp * 16; i < rend; i++) {
            float v1 = __uint_as_float(S[i * SS + lane]);
            float v2 = (lane < 24) ? __uint_as_float(S[i * SS + 32 + lane]) : -1e30f;
            float mx = fmaxf(v1, v2);
            #pragma unroll
            for (int o = 16; o > 0; o >>= 1) mx = fmaxf(mx, __shfl_xor_sync(0xffffffffu, mx, o));
            float e1 = __expf(v1 - mx);
            float e2 = (lane < 24) ? __expf(v2 - mx) : 0.f;
            float s = e1 + e2;
            #pragma unroll
            for (int o = 16; o > 0; o >>= 1) s += __shfl_xor_sync(0xffffffffu, s, o);
            float inv = 1.f / s;
            S[i * SS + lane] = f2tf32(e1 * inv);
            if (lane < 24) S[i * SS + 32 + lane] = f2tf32(e2 * inv);
        }
    }
    __syncwarp();

    {
        uint32_t pf[7][4];
        #pragma unroll
        for (int ks = 0; ks < 7; ks++) {
            int col = ks * 8 + (lane & 3);
            pf[ks][0] = S[rA * SS + col];
            pf[ks][1] = S[(rA + 8) * SS + col];
            pf[ks][2] = S[rA * SS + col + 4];
            pf[ks][3] = S[(rA + 8) * SS + col + 4];
        }
        float* outb = g_att + (size_t)w * N_TOK * C_DIM + h * HD;
        #pragma unroll
        for (int nt = 0; nt < 4; nt++) {
            float c[4] = {0.f, 0.f, 0.f, 0.f};
            #pragma unroll
            for (int ks = 0; ks < 7; ks++) {
                int kr = ks * 8 + (lane & 3);
                int nc = nt * 8 + (lane >> 2);
                uint32_t bf[2] = { Vs[kr * VS + nc], Vs[(kr + 4) * VS + nc] };
                mma_tf32(c, pf[ks], bf);
            }
            const int d = nt * 8 + 2 * (lane & 3);
            if (rA < N_TOK)
                *(float2*)&outb[rA * C_DIM + d] = make_float2(
                    __uint_as_float(f2tf32(c[0])), __uint_as_float(f2tf32(c[1])));
            if (rA + 8 < N_TOK)
                *(float2*)&outb[(rA + 8) * C_DIM + d] = make_float2(
                    __uint_as_float(f2tf32(c[2])), __uint_as_float(f2tf32(c[3])));
        }
    }
}

// ---------------- launch: chunked pipeline with cross-stream overlap ----------------
extern "C" void kernel_launch(void* const* d_in, const int* in_sizes, int n_in,
                              void* d_out, int out_size)
{
    const float* x          = (const float*)d_in[0];
    const float* mask       = (const float*)d_in[1];
    const float* qkv_w      = (const float*)d_in[2];
    const float* qkv_b      = (const float*)d_in[3];
    const float* proj_w     = (const float*)d_in[4];
    const float* proj_b     = (const float*)d_in[5];
    const float* bias_table = (const float*)d_in[6];
    const int*   rel_index  = (const int*)d_in[7];
    float*       out        = (float*)d_out;

    void* qkv_ptr = nullptr;
    void* att_ptr = nullptr;
    cudaGetSymbolAddress(&qkv_ptr, g_qkv);
    cudaGetSymbolAddress(&att_ptr, g_att);
    float* qkv = (float*)qkv_ptr;
    float* att = (float*)att_ptr;

    static cudaStream_t s1 = nullptr;
    static cudaEvent_t  evFork = nullptr;
    static cudaEvent_t  evA[N_CHUNKS] = {};
    static bool init_done = false;
    if (!init_done) {
        cudaFuncSetAttribute((const void*)gemm_tc_kernel<384, true, false>,
                             cudaFuncAttributeMaxDynamicSharedMemorySize, GEMM_SMEM);
        cudaFuncSetAttribute((const void*)gemm_tc_kernel<128, false, true>,
                             cudaFuncAttributeMaxDynamicSharedMemorySize, GEMM_SMEM);
        cudaStreamCreateWithFlags(&s1, cudaStreamNonBlocking);
        cudaEventCreateWithFlags(&evFork, cudaEventDisableTiming);
        for (int c = 0; c < N_CHUNKS; c++)
            cudaEventCreateWithFlags(&evA[c], cudaEventDisableTiming);
        init_done = true;
    }

    // origin stream (0): bm first, then fork
    bm_kernel<<<(NWIN * N_TOK * N_TOK + 255) / 256, 256>>>(mask, bias_table, rel_index);
    cudaEventRecord(evFork, 0);
    cudaStreamWaitEvent(s1, evFork, 0);

    // stream s1: all stage-A chunks, sequential, each publishing an event
    for (int c = 0; c < N_CHUNKS; c++) {
        const size_t roff = (size_t)c * CHUNK_M;
        gemm_tc_kernel<384, true, false>
            <<<dim3(384 / 128, CHUNK_M / 128), 256, GEMM_SMEM, s1>>>(
                x + roff * 128, qkv_w, qkv_b, qkv + roff * 384);
        cudaEventRecord(evA[c], s1);
    }

    // origin stream: B_c waits A_c, then C_c; overlaps with A_{c+1..} on s1
    for (int c = 0; c < N_CHUNKS; c++) {
        const size_t roff = (size_t)c * CHUNK_M;
        cudaStreamWaitEvent(0, evA[c], 0);
        attn_tc_kernel<<<dim3(CHUNK_W, NH), 128>>>(c * CHUNK_W);
        gemm_tc_kernel<128, false, true>
            <<<dim3(1, CHUNK_M / 128), 256, GEMM_SMEM>>>(
                att + roff * 128, proj_w, proj_b, out + roff * 128);
    }
}

// round 16
// speedup vs baseline: 1.1485x; 1.1485x over previous
#include <cuda_runtime.h>
#include <cstdint>
#include <cstddef>

// ---------------- problem constants ----------------
#define B_WIN   4096
#define N_TOK   49
#define C_DIM   128
#define NH      4
#define HD      32
#define NWIN    64
#define M_ROWS  (B_WIN * N_TOK)        // 200704
#define SCALE   0.17677669529663687f   // 32^-0.5

// ---------------- scratch (no cudaMalloc allowed) ----------------
__device__ __align__(16) float g_qkv[(size_t)M_ROWS * 384];  // tf32 BITS, q pre-scaled
__device__ __align__(16) float g_att[(size_t)M_ROWS * 128];  // tf32 BITS
__device__ __align__(16) float g_w1[128 * 384];              // qkv_w tf32 BITS
__device__ __align__(16) float g_w2[128 * 128];              // proj_w tf32 BITS
__device__ __align__(16) float g_bm[NWIN * N_TOK * N_TOK];   // bias[rel] + mask

// ---------------- helpers ----------------
__device__ __forceinline__ uint32_t f2tf32(float f) {
    uint32_t r;
    asm("cvt.rna.tf32.f32 %0, %1;" : "=r"(r) : "f"(f));
    return r;
}
__device__ __forceinline__ void mma_tf32(float c[4], const uint32_t a[4], const uint32_t b[2]) {
    asm volatile(
        "mma.sync.aligned.m16n8k8.row.col.f32.tf32.tf32.f32 "
        "{%0,%1,%2,%3}, {%4,%5,%6,%7}, {%8,%9}, {%0,%1,%2,%3};"
        : "+f"(c[0]), "+f"(c[1]), "+f"(c[2]), "+f"(c[3])
        : "r"(a[0]), "r"(a[1]), "r"(a[2]), "r"(a[3]), "r"(b[0]), "r"(b[1]));
}
__device__ __forceinline__ void cp_async16(uint32_t smem_dst, const void* gsrc) {
    asm volatile("cp.async.ca.shared.global [%0], [%1], 16;\n" :: "r"(smem_dst), "l"(gsrc));
}
__device__ __forceinline__ void cp_commit() { asm volatile("cp.async.commit_group;\n"); }
template <int N>
__device__ __forceinline__ void cp_wait() { asm volatile("cp.async.wait_group %0;\n" :: "n"(N)); }

// ---------------- prep: tf32 weights + g_bm table -----------------------------------
__global__ void prep_kernel(const float* __restrict__ mask,
                            const float* __restrict__ bias_table,
                            const int*   __restrict__ rel_index,
                            const float* __restrict__ qkv_w,
                            const float* __restrict__ proj_w)
{
    int idx = blockIdx.x * 256 + threadIdx.x;
    const int n1 = 128 * 384, n2 = 128 * 128, n3 = NWIN * N_TOK * N_TOK;
    if (idx < n1) {
        g_w1[idx] = __uint_as_float(f2tf32(qkv_w[idx]));
    } else if (idx < n1 + n2) {
        int t = idx - n1;
        g_w2[t] = __uint_as_float(f2tf32(proj_w[t]));
    } else if (idx < n1 + n2 + n3) {
        int t = idx - n1 - n2;
        g_bm[t] = mask[t] + bias_table[rel_index[t % (N_TOK * N_TOK)]];
    }
}

// ---------------- tf32 GEMM, cp.async double-buffered (r13 structure) ---------------
// out[M,NCOLS] = A[M,128] @ W[128,NCOLS] + bias. Tile 128x128, K chunks of 32.
// Grid: (n_blocks, m_blocks). W always pre-converted tf32 bits. A_TF32: A tf32 bits.
#define AS_STRIDE 36
#define BS_STRIDE 136
#define AS_WORDS (128 * AS_STRIDE)
#define BS_WORDS (32 * BS_STRIDE)
#define GEMM_SMEM ((2 * AS_WORDS + 2 * BS_WORDS) * 4)   // 71680 B

template <int NCOLS, bool QKV_OUT, bool A_TF32>
__global__ __launch_bounds__(256, 2)
void gemm_tc_kernel(const float* __restrict__ A,
                    const float* __restrict__ W,      // tf32 bits
                    const float* __restrict__ bias,
                    float* __restrict__ out)
{
    extern __shared__ float smem[];
    float* As = smem;                 // [2][AS_WORDS]
    float* Bs = smem + 2 * AS_WORDS;  // [2][BS_WORDS]

    const int tid  = threadIdx.x;
    const int lane = tid & 31;
    const int warp = tid >> 5;
    const int wm   = warp >> 2;
    const int wn   = warp & 3;
    const int m0   = blockIdx.y * 128;
    const int n0   = blockIdx.x * 128;

    float acc[4][4][4];
    #pragma unroll
    for (int i = 0; i < 4; i++)
        #pragma unroll
        for (int j = 0; j < 4; j++)
            #pragma unroll
            for (int r = 0; r < 4; r++) acc[i][j][r] = 0.f;

    auto stage_load = [&](int st, int k0) {
        #pragma unroll
        for (int p = 0; p < 4; p++) {
            int idx = tid + p * 256;
            int row = idx >> 3, seg = idx & 7;
            uint32_t dst = (uint32_t)__cvta_generic_to_shared(
                &As[st * AS_WORDS + row * AS_STRIDE + seg * 4]);
            cp_async16(dst, &A[(size_t)(m0 + row) * 128 + k0 + seg * 4]);
        }
        #pragma unroll
        for (int p = 0; p < 4; p++) {
            int idx = tid + p * 256;
            int row = idx >> 5, seg = idx & 31;
            uint32_t dst = (uint32_t)__cvta_generic_to_shared(
                &Bs[st * BS_WORDS + row * BS_STRIDE + seg * 4]);
            cp_async16(dst, &W[(size_t)(k0 + row) * NCOLS + n0 + seg * 4]);
        }
        cp_commit();
    };

    stage_load(0, 0);

    #pragma unroll
    for (int ch = 0; ch < 4; ch++) {
        if (ch < 3) stage_load((ch + 1) & 1, (ch + 1) * 32);
        if (ch < 3) cp_wait<1>(); else cp_wait<0>();
        __syncthreads();

        const float* as = &As[(ch & 1) * AS_WORDS];
        const float* bs = &Bs[(ch & 1) * BS_WORDS];

        #pragma unroll
        for (int kk = 0; kk < 4; kk++) {
            const int k = kk * 8;
            uint32_t af[4][4];
            #pragma unroll
            for (int mt = 0; mt < 4; mt++) {
                int row = wm * 64 + mt * 16 + (lane >> 2);
                int col = k + (lane & 3);
                if (A_TF32) {
                    af[mt][0] = __float_as_uint(as[row * AS_STRIDE + col]);
                    af[mt][1] = __float_as_uint(as[(row + 8) * AS_STRIDE + col]);
                    af[mt][2] = __float_as_uint(as[row * AS_STRIDE + col + 4]);
                    af[mt][3] = __float_as_uint(as[(row + 8) * AS_STRIDE + col + 4]);
                } else {
                    af[mt][0] = f2tf32(as[row * AS_STRIDE + col]);
                    af[mt][1] = f2tf32(as[(row + 8) * AS_STRIDE + col]);
                    af[mt][2] = f2tf32(as[row * AS_STRIDE + col + 4]);
                    af[mt][3] = f2tf32(as[(row + 8) * AS_STRIDE + col + 4]);
                }
            }
            uint32_t bf[4][2];
            #pragma unroll
            for (int nt = 0; nt < 4; nt++) {
                int col = wn * 32 + nt * 8 + (lane >> 2);
                int row = k + (lane & 3);
                bf[nt][0] = __float_as_uint(bs[row * BS_STRIDE + col]);
                bf[nt][1] = __float_as_uint(bs[(row + 4) * BS_STRIDE + col]);
            }
            #pragma unroll
            for (int mt = 0; mt < 4; mt++)
                #pragma unroll
                for (int nt = 0; nt < 4; nt++)
                    mma_tf32(acc[mt][nt], af[mt], bf[nt]);
        }
        __syncthreads();
    }

    #pragma unroll
    for (int mt = 0; mt < 4; mt++) {
        #pragma unroll
        for (int nt = 0; nt < 4; nt++) {
            int m = m0 + wm * 64 + mt * 16 + (lane >> 2);
            int n = n0 + wn * 32 + nt * 8 + (lane & 3) * 2;
            float b0 = bias[n], b1 = bias[n + 1];
            float v00 = acc[mt][nt][0] + b0, v01 = acc[mt][nt][1] + b1;
            float v10 = acc[mt][nt][2] + b0, v11 = acc[mt][nt][3] + b1;
            if (QKV_OUT) {
                float s0 = (n     < 128) ? SCALE : 1.f;
                float s1 = (n + 1 < 128) ? SCALE : 1.f;
                *(float2*)&out[(size_t)m * NCOLS + n] = make_float2(
                    __uint_as_float(f2tf32(v00 * s0)), __uint_as_float(f2tf32(v01 * s1)));
                *(float2*)&out[(size_t)(m + 8) * NCOLS + n] = make_float2(
                    __uint_as_float(f2tf32(v10 * s0)), __uint_as_float(f2tf32(v11 * s1)));
            } else {
                *(float2*)&out[(size_t)m * NCOLS + n] = make_float2(v00, v01);
                *(float2*)&out[(size_t)(m + 8) * NCOLS + n] = make_float2(v10, v11);
            }
        }
    }
}

// ---------------- tensor-core window attention (r13-proven, verbatim) ---------------
#define KS 36
#define VS 40
#define SS 60

__global__ __launch_bounds__(128)
void attn_tc_kernel()
{
    const int w = blockIdx.x;
    const int h = blockIdx.y;

    __shared__ __align__(16) uint32_t Ks[64 * KS];
    __shared__ __align__(16) uint32_t Vs[64 * VS];
    __shared__ __align__(16) uint32_t S [64 * SS];

    const int tid  = threadIdx.x;
    const int lane = tid & 31;
    const int warp = tid >> 5;

    // ---- async-stage k/v head slices (tf32 bits) ----
    const float* bq = g_qkv + (size_t)w * N_TOK * 384 + h * HD;
    for (int t = tid; t < N_TOK * 8 * 2; t += 128) {
        int tt = t / (N_TOK * 8);                  // 0 = K, 1 = V
        int rem = t - tt * (N_TOK * 8);
        int n = rem >> 3, seg = rem & 7;
        const float* src = bq + n * 384 + (tt + 1) * 128 + seg * 4;
        uint32_t dst = tt == 0
            ? (uint32_t)__cvta_generic_to_shared(&Ks[n * KS + seg * 4])
            : (uint32_t)__cvta_generic_to_shared(&Vs[n * VS + seg * 4]);
        cp_async16(dst, src);
    }
    cp_commit();

    // ---- Q fragments direct from gmem (tf32 bits, pre-scaled; rows clamped) ----
    const int rA = warp * 16 + (lane >> 2);
    uint32_t af[4][4];
    {
        const uint32_t* qb = (const uint32_t*)bq;
        int r0 = min(rA,     N_TOK - 1);
        int r1 = min(rA + 8, N_TOK - 1);
        #pragma unroll
        for (int ks = 0; ks < 4; ks++) {
            int col = ks * 8 + (lane & 3);
            af[ks][0] = qb[r0 * 384 + col];
            af[ks][1] = qb[r1 * 384 + col];
            af[ks][2] = qb[r0 * 384 + col + 4];
            af[ks][3] = qb[r1 * 384 + col + 4];
        }
    }

    // zero pad rows 49..63 of K and V
    for (int t = tid; t < 15 * HD; t += 128) {
        int n = N_TOK + (t >> 5), d = t & 31;
        Ks[n * KS + d] = 0u;
        Vs[n * VS + d] = 0u;
    }
    cp_wait<0>();
    __syncthreads();   // only block barrier

    // ---- scores for this warp's 16 rows ----
    const float* bm = g_bm + (size_t)(w & (NWIN - 1)) * N_TOK * N_TOK;
    {
        #pragma unroll
        for (int nt = 0; nt < 7; nt++) {
            float c[4] = {0.f, 0.f, 0.f, 0.f};
            #pragma unroll
            for (int ks = 0; ks < 4; ks++) {
                int nc = nt * 8 + (lane >> 2);
                int kr = ks * 8 + (lane & 3);
                uint32_t bf[2] = { Ks[nc * KS + kr], Ks[nc * KS + kr + 4] };
                mma_tf32(c, af[ks], bf);
            }
            const int j = nt * 8 + 2 * (lane & 3);
            #pragma unroll
            for (int half = 0; half < 2; half++) {
                int ii = rA + half * 8;
                float o0, o1;
                if (ii < N_TOK) {
                    o0 = (j     < N_TOK) ? c[half * 2]     + __ldg(&bm[ii * N_TOK + j])     : -1e30f;
                    o1 = (j + 1 < N_TOK) ? c[half * 2 + 1] + __ldg(&bm[ii * N_TOK + j + 1]) : -1e30f;
                } else { o0 = 0.f; o1 = 0.f; }
                S[ii * SS + j]     = __float_as_uint(o0);
                S[ii * SS + j + 1] = __float_as_uint(o1);
            }
        }
    }
    __syncwarp();

    // ---- softmax on own rows, writeback tf32 bits (P) ----
    {
        const int rend = min(warp * 16 + 16, N_TOK);
        for (int i = warp * 16; i < rend; i++) {
            float v1 = __uint_as_float(S[i * SS + lane]);
            float v2 = (lane < 24) ? __uint_as_float(S[i * SS + 32 + lane]) : -1e30f;
            float mx = fmaxf(v1, v2);
            #pragma unroll
            for (int o = 16; o > 0; o >>= 1) mx = fmaxf(mx, __shfl_xor_sync(0xffffffffu, mx, o));
            float e1 = __expf(v1 - mx);
            float e2 = (lane < 24) ? __expf(v2 - mx) : 0.f;
            float s = e1 + e2;
            #pragma unroll
            for (int o = 16; o > 0; o >>= 1) s += __shfl_xor_sync(0xffffffffu, s, o);
            float inv = 1.f / s;
            S[i * SS + lane] = f2tf32(e1 * inv);
            if (lane < 24) S[i * SS + 32 + lane] = f2tf32(e2 * inv);
        }
    }
    __syncwarp();

    // ---- O = P @ V for this warp's rows, store tf32 bits to g_att ----
    {
        uint32_t pf[7][4];
        #pragma unroll
        for (int ks = 0; ks < 7; ks++) {
            int col = ks * 8 + (lane & 3);
            pf[ks][0] = S[rA * SS + col];
            pf[ks][1] = S[(rA + 8) * SS + col];
            pf[ks][2] = S[rA * SS + col + 4];
            pf[ks][3] = S[(rA + 8) * SS + col + 4];
        }
        float* outb = g_att + (size_t)w * N_TOK * C_DIM + h * HD;
        #pragma unroll
        for (int nt = 0; nt < 4; nt++) {
            float c[4] = {0.f, 0.f, 0.f, 0.f};
            #pragma unroll
            for (int ks = 0; ks < 7; ks++) {
                int kr = ks * 8 + (lane & 3);
                int nc = nt * 8 + (lane >> 2);
                uint32_t bf[2] = { Vs[kr * VS + nc], Vs[(kr + 4) * VS + nc] };
                mma_tf32(c, pf[ks], bf);
            }
            const int d = nt * 8 + 2 * (lane & 3);
            if (rA < N_TOK)
                *(float2*)&outb[rA * C_DIM + d] = make_float2(
                    __uint_as_float(f2tf32(c[0])), __uint_as_float(f2tf32(c[1])));
            if (rA + 8 < N_TOK)
                *(float2*)&outb[(rA + 8) * C_DIM + d] = make_float2(
                    __uint_as_float(f2tf32(c[2])), __uint_as_float(f2tf32(c[3])));
        }
    }
}

// ---------------- launch ----------------
extern "C" void kernel_launch(void* const* d_in, const int* in_sizes, int n_in,
                              void* d_out, int out_size)
{
    const float* x          = (const float*)d_in[0];
    const float* mask       = (const float*)d_in[1];
    const float* qkv_w      = (const float*)d_in[2];
    const float* qkv_b      = (const float*)d_in[3];
    const float* proj_w     = (const float*)d_in[4];
    const float* proj_b     = (const float*)d_in[5];
    const float* bias_table = (const float*)d_in[6];
    const int*   rel_index  = (const int*)d_in[7];
    float*       out        = (float*)d_out;

    void* qkv_ptr = nullptr;
    void* att_ptr = nullptr;
    void* w1_ptr  = nullptr;
    void* w2_ptr  = nullptr;
    cudaGetSymbolAddress(&qkv_ptr, g_qkv);
    cudaGetSymbolAddress(&att_ptr, g_att);
    cudaGetSymbolAddress(&w1_ptr,  g_w1);
    cudaGetSymbolAddress(&w2_ptr,  g_w2);

    static bool attr_set = false;
    if (!attr_set) {
        cudaFuncSetAttribute((const void*)gemm_tc_kernel<384, true, false>,
                             cudaFuncAttributeMaxDynamicSharedMemorySize, GEMM_SMEM);
        cudaFuncSetAttribute((const void*)gemm_tc_kernel<128, false, true>,
                             cudaFuncAttributeMaxDynamicSharedMemorySize, GEMM_SMEM);
        attr_set = true;
    }

    // prep: tf32 weights + bias+mask table
    const int prep_total = 128 * 384 + 128 * 128 + NWIN * N_TOK * N_TOK;
    prep_kernel<<<(prep_total + 255) / 256, 256>>>(
        mask, bias_table, rel_index, qkv_w, proj_w);

    // Stage A: qkv (tf32 bits, q pre-scaled). Grid (n, m): A-tile L2 reuse.
    gemm_tc_kernel<384, true, false><<<dim3(384 / 128, M_ROWS / 128), 256, GEMM_SMEM>>>(
        x, (const float*)w1_ptr, qkv_b, (float*)qkv_ptr);

    // Stage B: tensor-core windowed attention (Q from gmem)
    attn_tc_kernel<<<dim3(B_WIN, NH), 128>>>();

    // Stage C: out = att @ proj_w + proj_b (both sides tf32 bits)
    gemm_tc_kernel<128, false, true><<<dim3(1, M_ROWS / 128), 256, GEMM_SMEM>>>(
        (const float*)att_ptr, (const float*)w2_ptr, proj_b, out);
}